// round 16
// baseline (speedup 1.0000x reference)
#include <cuda_runtime.h>

#define VERT   16384
#define D      256
#define DEG    128
#define S      32
#define SENT   99999
#define TILE_M 64
#define NTILES (VERT / TILE_M)     // 256
#define THREADS 256
#define BK     8
#define ASTR   68
#define NSTEP  (D / BK)
#define SMEM_PAD (120 * 1024)      // forces 1 gemm CTA per SM (2x120KB > 228KB)

// 16 MB static scratch for l = features[ids] @ W + b, plus per-tile ready flags
__device__ float g_l[VERT * D];
__device__ int   g_flag[NTILES];

// packed fp32x2 FMA (exact fp32 per half, 2x FFMA throughput on sm_103a)
__device__ __forceinline__ void fma2(unsigned long long &d, unsigned long long a,
                                     unsigned long long b) {
    asm("fma.rn.f32x2 %0, %1, %2, %0;" : "+l"(d) : "l"(a), "l"(b));
}
__device__ __forceinline__ unsigned long long pack2(float x) {
    unsigned long long r;
    asm("mov.b64 %0, {%1, %1};" : "=l"(r) : "f"(x));
    return r;
}
union F2U { unsigned long long u; float2 f; };

// ---------------------------------------------------------------------------
// Kernel 1 (producer): l = features[ids] @ W + b -> g_l, publish per-tile flag.
// R7's exact inner loop / tile / grid. Dynamic-smem padding forces 1 CTA/SM so
// one sampler CTA co-resides on EVERY SM for the gemm's whole duration.
// 256 CTAs run as two waves (148 + 108).
// ---------------------------------------------------------------------------
__global__ __launch_bounds__(THREADS)
void gemm_kernel(const int* __restrict__ ids,
                 const float* __restrict__ features,
                 const float* __restrict__ W,
                 const float* __restrict__ bias)
{
    extern __shared__ float smem[];
    float* As   = smem;                        // [2][BK*ASTR]
    float* Bs   = As + 2 * BK * ASTR;          // [2][BK*D]
    int*   grow = (int*)(Bs + 2 * BK * D);     // [TILE_M]

    const int tid = threadIdx.x;
    const int m0  = blockIdx.x * TILE_M;

    if (tid < TILE_M) grow[tid] = ids[m0 + tid];
    __syncthreads();

    const int rg = tid >> 5;
    const int cg = tid & 31;
    const int am = tid >> 1;
    const int ah = tid & 1;

    unsigned long long acc[4][8];
#pragma unroll
    for (int i = 0; i < 4; i++)
#pragma unroll
        for (int j = 0; j < 8; j++) acc[i][j] = 0ull;

    // ---- preload tile 0 ----
    if (tid < 128) {
        float4 a = *(const float4*)&features[(size_t)grow[am] * D + ah * 4];
#pragma unroll
        for (int j = 0; j < 4; j++)
            As[(ah * 4 + j) * ASTR + am] = ((const float*)&a)[j];
    }
#pragma unroll
    for (int p = 0; p < 2; p++) {
        int e  = tid + p * THREADS;
        int kk = e >> 6;
        int n4 = (e & 63) * 4;
        *(float4*)&Bs[kk * D + n4] = *(const float4*)&W[(size_t)kk * D + n4];
    }
    __syncthreads();

    for (int step = 0; step < NSTEP; step++) {
        const int cur = step & 1;
        const int nxt = cur ^ 1;
        const int k1  = (step + 1) * BK;
        float* Asc = As + cur * BK * ASTR;
        float* Asn = As + nxt * BK * ASTR;
        float* Bsc = Bs + cur * BK * D;
        float* Bsn = Bs + nxt * BK * D;

        if (step + 1 < NSTEP) {
            if (tid < 128) {
                float4 a = *(const float4*)&features[(size_t)grow[am] * D + k1 + ah * 4];
#pragma unroll
                for (int j = 0; j < 4; j++)
                    Asn[(ah * 4 + j) * ASTR + am] = ((const float*)&a)[j];
            }
#pragma unroll
            for (int p = 0; p < 2; p++) {
                int e  = tid + p * THREADS;
                int kk = e >> 6;
                int n4 = (e & 63) * 4;
                *(float4*)&Bsn[kk * D + n4] = *(const float4*)&W[(size_t)(k1 + kk) * D + n4];
            }
        }

#pragma unroll
        for (int kk = 0; kk < BK; kk++) {
            ulonglong2 aP0 = *(ulonglong2*)&Asc[kk * ASTR + rg * 8];
            ulonglong2 aP1 = *(ulonglong2*)&Asc[kk * ASTR + rg * 8 + 4];
            unsigned long long a_[4] = {aP0.x, aP0.y, aP1.x, aP1.y};
            float4 b0 = *(float4*)&Bsc[kk * D + cg * 4];
            float4 b1 = *(float4*)&Bsc[kk * D + 128 + cg * 4];
            unsigned long long bb[8];
            bb[0] = pack2(b0.x); bb[1] = pack2(b0.y); bb[2] = pack2(b0.z); bb[3] = pack2(b0.w);
            bb[4] = pack2(b1.x); bb[5] = pack2(b1.y); bb[6] = pack2(b1.z); bb[7] = pack2(b1.w);
#pragma unroll
            for (int i2 = 0; i2 < 4; i2++)
#pragma unroll
                for (int j = 0; j < 8; j++)
                    fma2(acc[i2][j], a_[i2], bb[j]);
        }
        __syncthreads();
    }

    // ---- bias + store tile to g_l ----
    {
        float4 bias0 = *(const float4*)&bias[cg * 4];
        float4 bias1 = *(const float4*)&bias[128 + cg * 4];
        float bjs[8] = {bias0.x, bias0.y, bias0.z, bias0.w,
                        bias1.x, bias1.y, bias1.z, bias1.w};
#pragma unroll
        for (int i2 = 0; i2 < 4; i2++) {
            float lo[8], hi[8];
#pragma unroll
            for (int j = 0; j < 8; j++) {
                F2U u; u.u = acc[i2][j];
                lo[j] = u.f.x + bjs[j];
                hi[j] = u.f.y + bjs[j];
            }
            int r0 = m0 + rg * 8 + 2 * i2;
            *(float4*)&g_l[(size_t)r0 * D + cg * 4]             = make_float4(lo[0], lo[1], lo[2], lo[3]);
            *(float4*)&g_l[(size_t)r0 * D + 128 + cg * 4]       = make_float4(lo[4], lo[5], lo[6], lo[7]);
            *(float4*)&g_l[(size_t)(r0 + 1) * D + cg * 4]       = make_float4(hi[0], hi[1], hi[2], hi[3]);
            *(float4*)&g_l[(size_t)(r0 + 1) * D + 128 + cg * 4] = make_float4(hi[4], hi[5], hi[6], hi[7]);
        }
    }

    // publish tile
    __threadfence();
    __syncthreads();
    if (tid == 0) atomicExch(&g_flag[blockIdx.x], 1);
}

// ---------------------------------------------------------------------------
// Kernel 2 (consumer): waits on its tile's flag, then gathers + dots + writes.
// (byte-identical to R7/R15)
// ---------------------------------------------------------------------------
__global__ __launch_bounds__(THREADS, 3)
void sampler_kernel(const int* __restrict__ ids,
                    const int* __restrict__ unif_rand,
                    const int* __restrict__ adj_info,
                    const float* __restrict__ features,
                    float* __restrict__ out)
{
    const int warp = threadIdx.x >> 5;
    const int lane = threadIdx.x & 31;
    const int v    = blockIdx.x * 8 + warp;   // grid = VERT/8
    const int tile = blockIdx.x >> 3;         // 8 consumer blocks per gemm tile

    if (threadIdx.x == 0) {
        while (atomicAdd(&g_flag[tile], 0) == 0) __nanosleep(200);
    }
    __syncthreads();
    __threadfence();

    const int ga   = __ldg(&ids[v]);
    const int myur = __ldg(&unif_rand[lane]);
    const int nb   = __ldg(&adj_info[(size_t)ga * DEG + myur]);

    float4 l0 = *(const float4*)&g_l[(size_t)v * D + 4 * lane];
    float4 l1 = *(const float4*)&g_l[(size_t)v * D + 128 + 4 * lane];

    int r0n = __shfl_sync(0xffffffffu, nb, 0);
    int r1n = __shfl_sync(0xffffffffu, nb, 1);
    const float4* q0 = (const float4*)&features[(size_t)r0n * D];
    const float4* q1 = (const float4*)&features[(size_t)r1n * D];
    float4 A0 = q0[lane], B0 = q0[32 + lane];
    float4 A1 = q1[lane], B1 = q1[32 + lane];

    float P[S];
#pragma unroll
    for (int s = 0; s < S; s++) {
        float4 ca  = (s & 1) ? A1 : A0;
        float4 cb4 = (s & 1) ? B1 : B0;
        if (s + 2 < S) {
            int rn = __shfl_sync(0xffffffffu, nb, s + 2);
            const float4* qn = (const float4*)&features[(size_t)rn * D];
            if (s & 1) { A1 = qn[lane]; B1 = qn[32 + lane]; }
            else       { A0 = qn[lane]; B0 = qn[32 + lane]; }
        }
        float tacc;
        tacc = ca.x * l0.x;
        tacc = fmaf(ca.y, l0.y, tacc);
        tacc = fmaf(ca.z, l0.z, tacc);
        tacc = fmaf(ca.w, l0.w, tacc);
        tacc = fmaf(cb4.x, l1.x, tacc);
        tacc = fmaf(cb4.y, l1.y, tacc);
        tacc = fmaf(cb4.z, l1.z, tacc);
        tacc = fmaf(cb4.w, l1.w, tacc);
        P[s] = tacc;
    }

    // Butterfly transpose-reduce: lane s ends with O[s] in P[0].
#pragma unroll
    for (int off = 16; off >= 1; off >>= 1) {
#pragma unroll
        for (int i = 0; i < off; i++) {
            float send = (lane & off) ? P[i] : P[i + off];
            float recv = __shfl_xor_sync(0xffffffffu, send, off);
            P[i] = ((lane & off) ? P[i + off] : P[i]) + recv;
        }
    }
    float myout = fmaxf(P[0], 0.0f);

    float mean = myout;
#pragma unroll
    for (int off = 16; off; off >>= 1)
        mean += __shfl_xor_sync(0xffffffffu, mean, off);
    mean *= (1.0f / S);

    const size_t attOff = (size_t)VERT * S;
    const size_t nzOff  = (size_t)VERT * S * 2;
    const size_t mnOff  = nzOff + VERT;

    const bool cond = (nb == SENT) || (myout > 0.5f * mean);
    out[(size_t)v * S + lane]          = (float)(cond ? SENT : nb);
    out[attOff + (size_t)v * S + lane] = 1.0f;

    float nz = cond ? 0.0f : 1.0f;
#pragma unroll
    for (int off = 16; off; off >>= 1)
        nz += __shfl_xor_sync(0xffffffffu, nz, off);
    if (lane == 0) {
        out[nzOff + v] = nz;
        out[mnOff + v] = mean;
    }
}

extern "C" void kernel_launch(void* const* d_in, const int* in_sizes, int n_in,
                              void* d_out, int out_size)
{
    (void)in_sizes; (void)n_in; (void)out_size;
    const int*   ids  = (const int*)d_in[0];
    const int*   urnd = (const int*)d_in[1];
    const int*   adj  = (const int*)d_in[2];
    const float* feat = (const float*)d_in[3];
    const float* W    = (const float*)d_in[4];
    const float* b    = (const float*)d_in[5];
    float*       out  = (float*)d_out;

    cudaFuncSetAttribute(gemm_kernel,
                         cudaFuncAttributeMaxDynamicSharedMemorySize, SMEM_PAD);

    // Sampler on a MINIMUM-priority stream: gemm (both waves) always wins
    // pending-CTA arbitration; sampler co-resides via leftover registers.
    cudaStream_t s2;
    int prLeast = 0, prGreatest = 0;
    if (cudaDeviceGetStreamPriorityRange(&prLeast, &prGreatest) == cudaSuccess) {
        if (cudaStreamCreateWithPriority(&s2, cudaStreamNonBlocking, prLeast)
            != cudaSuccess)
            cudaStreamCreateWithFlags(&s2, cudaStreamNonBlocking);
    } else {
        cudaStreamCreateWithFlags(&s2, cudaStreamNonBlocking);
    }

    cudaEvent_t e1, e2;
    cudaEventCreateWithFlags(&e1, cudaEventDisableTiming);
    cudaEventCreateWithFlags(&e2, cudaEventDisableTiming);

    // reset per-tile flags (graph-capturable, no allocation)
    void* flag_ptr = nullptr;
    cudaGetSymbolAddress(&flag_ptr, g_flag);
    cudaMemsetAsync(flag_ptr, 0, NTILES * sizeof(int));

    cudaEventRecord(e1, 0);
    cudaStreamWaitEvent(s2, e1, 0);

    // producer first (priority + dispatch order), consumer co-resides/backfills
    gemm_kernel<<<NTILES, THREADS, SMEM_PAD>>>(ids, feat, W, b);
    sampler_kernel<<<VERT / 8, THREADS, 0, s2>>>(ids, urnd, adj, feat, out);

    cudaEventRecord(e2, s2);
    cudaStreamWaitEvent(0, e2, 0);
}

// round 17
// speedup vs baseline: 1.1812x; 1.1812x over previous
#include <cuda_runtime.h>

#define VERT   16384
#define D      256
#define DEG    128
#define S      32
#define SENT   99999
#define TILE_M 64
#define NTILES (VERT / TILE_M)     // 256
#define THREADS 256
#define BK     8
#define ASTR   68
#define NSTEP  (D / BK)

// 16 MB static scratch for l = features[ids] @ W + b, plus per-tile ready flags
__device__ float g_l[VERT * D];
__device__ int   g_flag[NTILES];

// packed fp32x2 FMA (exact fp32 per half, 2x FFMA throughput on sm_103a)
__device__ __forceinline__ void fma2(unsigned long long &d, unsigned long long a,
                                     unsigned long long b) {
    asm("fma.rn.f32x2 %0, %1, %2, %0;" : "+l"(d) : "l"(a), "l"(b));
}
__device__ __forceinline__ unsigned long long pack2(float x) {
    unsigned long long r;
    asm("mov.b64 %0, {%1, %1};" : "=l"(r) : "f"(x));
    return r;
}
union F2U { unsigned long long u; float2 f; };

// ---------------------------------------------------------------------------
// Kernel 1 (producer): l = features[ids] @ W + b -> g_l, publish per-tile flag.
// 256 CTAs, one 64x256 tile each, 2/SM, 8x8 fp32x2 per-thread tile,
// double-buffered SMEM, one __syncthreads per k-step. (Best measured gemm.)
// ---------------------------------------------------------------------------
__global__ __launch_bounds__(THREADS, 2)
void gemm_kernel(const int* __restrict__ ids,
                 const float* __restrict__ features,
                 const float* __restrict__ W,
                 const float* __restrict__ bias)
{
    __shared__ float As[2][BK * ASTR];
    __shared__ float Bs[2][BK * D];
    __shared__ int   grow[TILE_M];

    const int tid = threadIdx.x;
    const int m0  = blockIdx.x * TILE_M;

    if (tid < TILE_M) grow[tid] = ids[m0 + tid];
    __syncthreads();

    const int rg = tid >> 5;
    const int cg = tid & 31;
    const int am = tid >> 1;
    const int ah = tid & 1;

    unsigned long long acc[4][8];
#pragma unroll
    for (int i = 0; i < 4; i++)
#pragma unroll
        for (int j = 0; j < 8; j++) acc[i][j] = 0ull;

    // ---- preload tile 0 ----
    if (tid < 128) {
        float4 a = *(const float4*)&features[(size_t)grow[am] * D + ah * 4];
#pragma unroll
        for (int j = 0; j < 4; j++)
            As[0][(ah * 4 + j) * ASTR + am] = ((const float*)&a)[j];
    }
#pragma unroll
    for (int p = 0; p < 2; p++) {
        int e  = tid + p * THREADS;
        int kk = e >> 6;
        int n4 = (e & 63) * 4;
        *(float4*)&Bs[0][kk * D + n4] = *(const float4*)&W[(size_t)kk * D + n4];
    }
    __syncthreads();

    for (int step = 0; step < NSTEP; step++) {
        const int cur = step & 1;
        const int nxt = cur ^ 1;
        const int k1  = (step + 1) * BK;

        if (step + 1 < NSTEP) {
            if (tid < 128) {
                float4 a = *(const float4*)&features[(size_t)grow[am] * D + k1 + ah * 4];
#pragma unroll
                for (int j = 0; j < 4; j++)
                    As[nxt][(ah * 4 + j) * ASTR + am] = ((const float*)&a)[j];
            }
#pragma unroll
            for (int p = 0; p < 2; p++) {
                int e  = tid + p * THREADS;
                int kk = e >> 6;
                int n4 = (e & 63) * 4;
                *(float4*)&Bs[nxt][kk * D + n4] = *(const float4*)&W[(size_t)(k1 + kk) * D + n4];
            }
        }

#pragma unroll
        for (int kk = 0; kk < BK; kk++) {
            ulonglong2 aP0 = *(ulonglong2*)&As[cur][kk * ASTR + rg * 8];
            ulonglong2 aP1 = *(ulonglong2*)&As[cur][kk * ASTR + rg * 8 + 4];
            unsigned long long a_[4] = {aP0.x, aP0.y, aP1.x, aP1.y};
            float4 b0 = *(float4*)&Bs[cur][kk * D + cg * 4];
            float4 b1 = *(float4*)&Bs[cur][kk * D + 128 + cg * 4];
            unsigned long long bb[8];
            bb[0] = pack2(b0.x); bb[1] = pack2(b0.y); bb[2] = pack2(b0.z); bb[3] = pack2(b0.w);
            bb[4] = pack2(b1.x); bb[5] = pack2(b1.y); bb[6] = pack2(b1.z); bb[7] = pack2(b1.w);
#pragma unroll
            for (int i2 = 0; i2 < 4; i2++)
#pragma unroll
                for (int j = 0; j < 8; j++)
                    fma2(acc[i2][j], a_[i2], bb[j]);
        }
        __syncthreads();
    }

    // ---- bias + store tile to g_l ----
    {
        float4 bias0 = *(const float4*)&bias[cg * 4];
        float4 bias1 = *(const float4*)&bias[128 + cg * 4];
        float bjs[8] = {bias0.x, bias0.y, bias0.z, bias0.w,
                        bias1.x, bias1.y, bias1.z, bias1.w};
#pragma unroll
        for (int i2 = 0; i2 < 4; i2++) {
            float lo[8], hi[8];
#pragma unroll
            for (int j = 0; j < 8; j++) {
                F2U u; u.u = acc[i2][j];
                lo[j] = u.f.x + bjs[j];
                hi[j] = u.f.y + bjs[j];
            }
            int r0 = m0 + rg * 8 + 2 * i2;
            *(float4*)&g_l[(size_t)r0 * D + cg * 4]             = make_float4(lo[0], lo[1], lo[2], lo[3]);
            *(float4*)&g_l[(size_t)r0 * D + 128 + cg * 4]       = make_float4(lo[4], lo[5], lo[6], lo[7]);
            *(float4*)&g_l[(size_t)(r0 + 1) * D + cg * 4]       = make_float4(hi[0], hi[1], hi[2], hi[3]);
            *(float4*)&g_l[(size_t)(r0 + 1) * D + 128 + cg * 4] = make_float4(hi[4], hi[5], hi[6], hi[7]);
        }
    }

    // publish tile
    __threadfence();
    __syncthreads();
    if (tid == 0) atomicExch(&g_flag[blockIdx.x], 1);
}

// ---------------------------------------------------------------------------
// Kernel 2 (consumer): waits on its tile's flag, then gathers + dots + writes.
// Contiguous 512B warp gathers (min L1 wavefronts) + butterfly transpose-reduce.
// ---------------------------------------------------------------------------
__global__ __launch_bounds__(THREADS, 3)
void sampler_kernel(const int* __restrict__ ids,
                    const int* __restrict__ unif_rand,
                    const int* __restrict__ adj_info,
                    const float* __restrict__ features,
                    float* __restrict__ out)
{
    const int warp = threadIdx.x >> 5;
    const int lane = threadIdx.x & 31;
    const int v    = blockIdx.x * 8 + warp;   // grid = VERT/8
    const int tile = blockIdx.x >> 3;         // 8 consumer blocks per gemm tile

    if (threadIdx.x == 0) {
        while (atomicAdd(&g_flag[tile], 0) == 0) __nanosleep(200);
    }
    __syncthreads();
    __threadfence();

    const int ga   = __ldg(&ids[v]);
    const int myur = __ldg(&unif_rand[lane]);
    const int nb   = __ldg(&adj_info[(size_t)ga * DEG + myur]);

    float4 l0 = *(const float4*)&g_l[(size_t)v * D + 4 * lane];
    float4 l1 = *(const float4*)&g_l[(size_t)v * D + 128 + 4 * lane];

    int r0n = __shfl_sync(0xffffffffu, nb, 0);
    int r1n = __shfl_sync(0xffffffffu, nb, 1);
    const float4* q0 = (const float4*)&features[(size_t)r0n * D];
    const float4* q1 = (const float4*)&features[(size_t)r1n * D];
    float4 A0 = q0[lane], B0 = q0[32 + lane];
    float4 A1 = q1[lane], B1 = q1[32 + lane];

    float P[S];
#pragma unroll
    for (int s = 0; s < S; s++) {
        float4 ca  = (s & 1) ? A1 : A0;
        float4 cb4 = (s & 1) ? B1 : B0;
        if (s + 2 < S) {
            int rn = __shfl_sync(0xffffffffu, nb, s + 2);
            const float4* qn = (const float4*)&features[(size_t)rn * D];
            if (s & 1) { A1 = qn[lane]; B1 = qn[32 + lane]; }
            else       { A0 = qn[lane]; B0 = qn[32 + lane]; }
        }
        float tacc;
        tacc = ca.x * l0.x;
        tacc = fmaf(ca.y, l0.y, tacc);
        tacc = fmaf(ca.z, l0.z, tacc);
        tacc = fmaf(ca.w, l0.w, tacc);
        tacc = fmaf(cb4.x, l1.x, tacc);
        tacc = fmaf(cb4.y, l1.y, tacc);
        tacc = fmaf(cb4.z, l1.z, tacc);
        tacc = fmaf(cb4.w, l1.w, tacc);
        P[s] = tacc;
    }

    // Butterfly transpose-reduce: lane s ends with O[s] in P[0].
#pragma unroll
    for (int off = 16; off >= 1; off >>= 1) {
#pragma unroll
        for (int i = 0; i < off; i++) {
            float send = (lane & off) ? P[i] : P[i + off];
            float recv = __shfl_xor_sync(0xffffffffu, send, off);
            P[i] = ((lane & off) ? P[i + off] : P[i]) + recv;
        }
    }
    float myout = fmaxf(P[0], 0.0f);

    float mean = myout;
#pragma unroll
    for (int off = 16; off; off >>= 1)
        mean += __shfl_xor_sync(0xffffffffu, mean, off);
    mean *= (1.0f / S);

    const size_t attOff = (size_t)VERT * S;
    const size_t nzOff  = (size_t)VERT * S * 2;
    const size_t mnOff  = nzOff + VERT;

    const bool cond = (nb == SENT) || (myout > 0.5f * mean);
    out[(size_t)v * S + lane]          = (float)(cond ? SENT : nb);
    out[attOff + (size_t)v * S + lane] = 1.0f;

    float nz = cond ? 0.0f : 1.0f;
#pragma unroll
    for (int off = 16; off; off >>= 1)
        nz += __shfl_xor_sync(0xffffffffu, nz, off);
    if (lane == 0) {
        out[nzOff + v] = nz;
        out[mnOff + v] = mean;
    }
}

extern "C" void kernel_launch(void* const* d_in, const int* in_sizes, int n_in,
                              void* d_out, int out_size)
{
    (void)in_sizes; (void)n_in; (void)out_size;
    const int*   ids  = (const int*)d_in[0];
    const int*   urnd = (const int*)d_in[1];
    const int*   adj  = (const int*)d_in[2];
    const float* feat = (const float*)d_in[3];
    const float* W    = (const float*)d_in[4];
    const float* b    = (const float*)d_in[5];
    float*       out  = (float*)d_out;

    // Sampler on a MINIMUM-priority stream so the dispatcher places all gemm
    // CTAs into wave-1 slots first; sampler CTAs deterministically backfill
    // as gemm CTAs retire. Fall back to a plain stream if priorities are
    // unavailable in this container.
    cudaStream_t s2;
    int prLeast = 0, prGreatest = 0;
    if (cudaDeviceGetStreamPriorityRange(&prLeast, &prGreatest) == cudaSuccess) {
        if (cudaStreamCreateWithPriority(&s2, cudaStreamNonBlocking, prLeast)
            != cudaSuccess)
            cudaStreamCreateWithFlags(&s2, cudaStreamNonBlocking);
    } else {
        cudaStreamCreateWithFlags(&s2, cudaStreamNonBlocking);
    }

    cudaEvent_t e1, e2;
    cudaEventCreateWithFlags(&e1, cudaEventDisableTiming);
    cudaEventCreateWithFlags(&e2, cudaEventDisableTiming);

    // reset per-tile flags (graph-capturable, no allocation)
    void* flag_ptr = nullptr;
    cudaGetSymbolAddress(&flag_ptr, g_flag);
    cudaMemsetAsync(flag_ptr, 0, NTILES * sizeof(int));

    cudaEventRecord(e1, 0);
    cudaStreamWaitEvent(s2, e1, 0);

    // producer first (dispatch-order + priority), consumer backfills
    gemm_kernel<<<NTILES, THREADS>>>(ids, feat, W, b);
    sampler_kernel<<<VERT / 8, THREADS, 0, s2>>>(ids, urnd, adj, feat, out);

    cudaEventRecord(e2, s2);
    cudaStreamWaitEvent(0, e2, 0);
}